// round 7
// baseline (speedup 1.0000x reference)
#include <cuda_runtime.h>
#include <cstdint>

// WMeasure_Rot: elementwise quantum-measurement update.
// inputs:  d_in[0]=input f32, d_in[1]=angles f32, d_in[2]=last_res f32  (each B*N)
// output:  d_out[0:B*N) = meas_res,  d_out[B*N:2*B*N) = new_angles
//
// RNG (bit-exact, verified R1): JAX threefry2x32, key=(0,42), partitionable.
// R7: pipe rebalancing. ncu shows ALU 76.6% vs FMA 37.9% -- threefry's
// SHF+LOP3 are ALU-locked while the FMA pipe idles. Rewrite each rotate as
// rotl(x,d) = lo(x*2^d) | hi(x*2^d) via mul.wide.u32 (IMAD.WIDE, fma pipe),
// fused with the round xor into ONE 3-input LOP3: (lo|hi)^x0. Bit-exact.
// Same for the final >>9. Math otherwise identical to R5/R6 (1 flip).

#define DEVINL __device__ __forceinline__

// rotl32(x,d) ^ m, with the shift done on the FMA pipe (IMAD.WIDE) and the
// or+xor fused into a single LOP3. Exact: x*2^d (d<32) as u64 = (x<<d)|(x>>(32-d)) split.
DEVINL uint32_t rotxor(uint32_t x, int d, uint32_t m) {
    uint64_t w;
    asm("mul.wide.u32 %0, %1, %2;" : "=l"(w) : "r"(x), "r"(1u << d));
    uint32_t lo = (uint32_t)w;
    uint32_t hi = (uint32_t)(w >> 32);
    return (lo | hi) ^ m;
}

DEVINL uint32_t threefry_bits(uint32_t ctr) {
    const uint32_t ks0 = 0u;
    const uint32_t ks1 = 42u;
    const uint32_t ks2 = 0x1BD11BDAu ^ 0u ^ 42u;
    uint32_t x0 = 0u + ks0;     // hi counter word = 0
    uint32_t x1 = ctr + ks1;    // lo counter word = element index
#define TF_ROUND(r) { x0 += x1; x1 = rotxor(x1, (r), x0); }
    TF_ROUND(13) TF_ROUND(15) TF_ROUND(26) TF_ROUND(6)
    x0 += ks1; x1 += ks2 + 1u;
    TF_ROUND(17) TF_ROUND(29) TF_ROUND(16) TF_ROUND(24)
    x0 += ks2; x1 += ks0 + 2u;
    TF_ROUND(13) TF_ROUND(15) TF_ROUND(26) TF_ROUND(6)
    x0 += ks0; x1 += ks1 + 3u;
    TF_ROUND(17) TF_ROUND(29) TF_ROUND(16) TF_ROUND(24)
    x0 += ks1; x1 += ks2 + 4u;
    TF_ROUND(13) TF_ROUND(15) TF_ROUND(26) TF_ROUND(6)
    x0 += ks2; x1 += ks0 + 5u;
#undef TF_ROUND
    return x0 ^ x1;
}

// ((bits >> 9) | 0x3f800000) with the shift on the FMA pipe: hi(bits * 2^23).
DEVINL float bits_to_f(uint32_t bits) {
    uint64_t w;
    asm("mul.wide.u32 %0, %1, %2;" : "=l"(w) : "r"(bits), "r"(1u << 23));
    uint32_t hi = (uint32_t)(w >> 32);
    return __uint_as_float(hi | 0x3f800000u);
}

DEVINL float mufu_ex2(float x)  { float r; asm("ex2.approx.f32 %0, %1;"  : "=f"(r) : "f"(x)); return r; }
DEVINL float mufu_rcp(float x)  { float r; asm("rcp.approx.f32 %0, %1;"  : "=f"(r) : "f"(x)); return r; }
DEVINL float mufu_rsq(float x)  { float r; asm("rsqrt.approx.f32 %0, %1;": "=f"(r) : "f"(x)); return r; }
DEVINL float mufu_sqrt(float x) { float r; asm("sqrt.approx.f32 %0, %1;" : "=f"(r) : "f"(x)); return r; }
DEVINL float mufu_sin(float x)  { float r; asm("sin.approx.f32 %0, %1;"  : "=f"(r) : "f"(x)); return r; }

DEVINL void wmeas_elem(float x, float a, float lr, uint32_t idx,
                       float& meas_out, float& nang_out) {
    const float PI_4       = 0.7853981633974483f;   // pi/4
    const float PI_2       = 1.5707963267948966f;   // pi/2
    const float SIN_G      = 0.70710678f;           // f32(sin(pi/4))
    const float FOURLOG2E  = 5.770780163555852f;    // 4/ln(2)
    const float K_MID      = 0.6532814824381883f;   // (K_PLUS+K_MINUS)/2
    const float K_HDF      = 0.2705980500730985f;   // (K_MINUS-K_PLUS)/2

    // f in [1,2): u = f - 1 exactly (Sterbenz)
    float f = bits_to_f(threefry_bits(idx));

    // tanh(2x) = 1 - 2*rcp(e^{4x}+1); ex2->inf->rcp->0 saturates exactly.
    float e  = mufu_ex2(x * FOURLOG2E);
    float r  = mufu_rcp(e + 1.0f);
    float base = fmaf(PI_4, lr - 1.0f, 0.5f * a);   // lr-1 in {0,-2}: exact
    float ht = fmaf(PI_2, r, base);

    float s  = mufu_sin(ht);                        // betas
    float ez = fmaf(-2.0f * SIN_G * s, s, SIN_G);   // sin(g)*cos(t), |ez|<=0.7071
    float hez = 0.5f * ez;

    // reference: u < p0/(p0+p1) ~ (1+ez)/2; here: f < 1.5 + ez/2
    float meas = (f < hez + 1.5f) ? 1.0f : -1.0f;

    // side = s * K(meas) * rsqrt(p)
    float p = fmaf(meas, hez, 0.5f);                // in [0.146, 0.854]
    float K = fmaf(meas, -K_HDF, K_MID);
    float side = (s * K) * mufu_rsq(p);

    // 2*asin(side): A&S 4.4.45 deg-3, coefficients pre-doubled
    float aa = fminf(fabsf(side), 1.0f);
    float sq = mufu_sqrt(1.0f - aa);
    float poly = -0.0374586f;
    poly = fmaf(poly, aa, 0.1485220f);
    poly = fmaf(poly, aa, -0.4242288f);
    poly = fmaf(poly, aa, 3.1414576f);
    float v = fmaf(-sq, poly, 3.14159265358979f);   // 2*asin(|side|)

    meas_out = meas;
    nang_out = copysignf(v, side);
}

__global__ void __launch_bounds__(256)
wmeasure_rot_kernel(const float4* __restrict__ inp,
                    const float4* __restrict__ ang,
                    const float4* __restrict__ lres,
                    float4* __restrict__ out_meas,
                    float4* __restrict__ out_ang) {
    int t = blockIdx.x * blockDim.x + threadIdx.x;
    int s0 = 2 * t;              // two consecutive float4 slots per thread
    int s1 = 2 * t + 1;
    uint32_t base = (uint32_t)t * 8u;

    float4 x0 = inp[s0],  x1 = inp[s1];
    float4 a0 = ang[s0],  a1 = ang[s1];
    float4 l0 = lres[s0], l1 = lres[s1];

    float xs[8] = {x0.x, x0.y, x0.z, x0.w, x1.x, x1.y, x1.z, x1.w};
    float as[8] = {a0.x, a0.y, a0.z, a0.w, a1.x, a1.y, a1.z, a1.w};
    float ls[8] = {l0.x, l0.y, l0.z, l0.w, l1.x, l1.y, l1.z, l1.w};

    float ms[8], ns[8];
#pragma unroll
    for (int j = 0; j < 8; j++)
        wmeas_elem(xs[j], as[j], ls[j], base + (uint32_t)j, ms[j], ns[j]);

    out_meas[s0] = make_float4(ms[0], ms[1], ms[2], ms[3]);
    out_meas[s1] = make_float4(ms[4], ms[5], ms[6], ms[7]);
    out_ang[s0]  = make_float4(ns[0], ns[1], ns[2], ns[3]);
    out_ang[s1]  = make_float4(ns[4], ns[5], ns[6], ns[7]);
}

extern "C" void kernel_launch(void* const* d_in, const int* in_sizes, int n_in,
                              void* d_out, int out_size) {
    const float* inp  = (const float*)d_in[0];
    const float* ang  = (const float*)d_in[1];
    const float* lres = (const float*)d_in[2];
    float* out = (float*)d_out;

    int n = in_sizes[0];                 // B*N = 33554432 (divisible by 2048)
    int threads = n / 8;
    int block = 256;
    int grid = (threads + block - 1) / block;

    wmeasure_rot_kernel<<<grid, block>>>(
        (const float4*)inp, (const float4*)ang, (const float4*)lres,
        (float4*)out, (float4*)(out + n));
}

// round 8
// speedup vs baseline: 1.4278x; 1.4278x over previous
#include <cuda_runtime.h>
#include <cstdint>

// WMeasure_Rot: elementwise quantum-measurement update.
// inputs:  d_in[0]=input f32, d_in[1]=angles f32, d_in[2]=last_res f32  (each B*N)
// output:  d_out[0:B*N) = meas_res,  d_out[B*N:2*B*N) = new_angles
//
// RNG (bit-exact, verified R1): JAX threefry2x32, key=(0,42), partitionable.
// R8 = revert R7's IMAD.WIDE rotates (lengthened the serial threefry chain,
// kernel went latency-bound: issue 84->63%, dur 119->167us). Back to SHF
// rotates (R6 codegen) + two issue-count trims on the float side:
//   base chain 4 ops -> 3 via fma(PI_4, lr, -PI_4) (exact for lr=+-1)
//   hez directly:  fma(-SIN_G*s, s, SIN_G/2)  (3 ops -> 2, <=1 ulp shift)

#define DEVINL __device__ __forceinline__

DEVINL uint32_t rotl32(uint32_t x, int d) { return __funnelshift_l(x, x, d); }

DEVINL uint32_t threefry_bits(uint32_t ctr) {
    const uint32_t ks0 = 0u;
    const uint32_t ks1 = 42u;
    const uint32_t ks2 = 0x1BD11BDAu ^ 0u ^ 42u;
    uint32_t x0 = 0u + ks0;     // hi counter word = 0
    uint32_t x1 = ctr + ks1;    // lo counter word = element index
#define TF_ROUND(r) { x0 += x1; x1 = rotl32(x1, (r)); x1 ^= x0; }
    TF_ROUND(13) TF_ROUND(15) TF_ROUND(26) TF_ROUND(6)
    x0 += ks1; x1 += ks2 + 1u;
    TF_ROUND(17) TF_ROUND(29) TF_ROUND(16) TF_ROUND(24)
    x0 += ks2; x1 += ks0 + 2u;
    TF_ROUND(13) TF_ROUND(15) TF_ROUND(26) TF_ROUND(6)
    x0 += ks0; x1 += ks1 + 3u;
    TF_ROUND(17) TF_ROUND(29) TF_ROUND(16) TF_ROUND(24)
    x0 += ks1; x1 += ks2 + 4u;
    TF_ROUND(13) TF_ROUND(15) TF_ROUND(26) TF_ROUND(6)
    x0 += ks2; x1 += ks0 + 5u;
#undef TF_ROUND
    return x0 ^ x1;
}

DEVINL float mufu_ex2(float x)  { float r; asm("ex2.approx.f32 %0, %1;"  : "=f"(r) : "f"(x)); return r; }
DEVINL float mufu_rcp(float x)  { float r; asm("rcp.approx.f32 %0, %1;"  : "=f"(r) : "f"(x)); return r; }
DEVINL float mufu_rsq(float x)  { float r; asm("rsqrt.approx.f32 %0, %1;": "=f"(r) : "f"(x)); return r; }
DEVINL float mufu_sqrt(float x) { float r; asm("sqrt.approx.f32 %0, %1;" : "=f"(r) : "f"(x)); return r; }
DEVINL float mufu_sin(float x)  { float r; asm("sin.approx.f32 %0, %1;"  : "=f"(r) : "f"(x)); return r; }

DEVINL void wmeas_elem(float x, float a, float lr, uint32_t idx,
                       float& meas_out, float& nang_out) {
    const float PI_4       = 0.7853981633974483f;   // pi/4
    const float PI_2       = 1.5707963267948966f;   // pi/2
    const float SIN_G      = 0.70710678f;           // f32(sin(pi/4))
    const float HALF_SING  = 0.35355339f;           // SIN_G/2
    const float FOURLOG2E  = 5.770780163555852f;    // 4/ln(2)
    const float K_MID      = 0.6532814824381883f;   // (K_PLUS+K_MINUS)/2
    const float K_HDF      = 0.2705980500730985f;   // (K_MINUS-K_PLUS)/2

    // f in [1,2): u = f - 1 exactly (Sterbenz)
    uint32_t bits = threefry_bits(idx);
    float f = __uint_as_float((bits >> 9) | 0x3f800000u);

    // tanh(2x) = 1 - 2*rcp(e^{4x}+1); ex2->inf->rcp->0 saturates exactly.
    // ht = 0.5*a + (pi/4)*(lr-1) + (pi/2)*r, with (pi/4)(lr-1) = fma(pi/4,lr,-pi/4)
    float e  = mufu_ex2(x * FOURLOG2E);
    float r  = mufu_rcp(e + 1.0f);
    float bk = fmaf(PI_4, lr, -PI_4);               // exact for lr in {+1,-1}
    float b2 = fmaf(0.5f, a, bk);
    float ht = fmaf(PI_2, r, b2);

    float s   = mufu_sin(ht);                       // betas
    float hez = fmaf(-SIN_G * s, s, HALF_SING);     // (sin g * cos t)/2, |.|<=0.354

    // reference: u < p0/(p0+p1) ~ (1+ez)/2; here: f < 1.5 + hez
    float meas = (f < hez + 1.5f) ? 1.0f : -1.0f;

    // side = s * K(meas) * rsqrt(p),  p = (1+meas*ez)/2
    float p = fmaf(meas, hez, 0.5f);                // in [0.146, 0.854]
    float K = fmaf(meas, -K_HDF, K_MID);
    float side = (s * K) * mufu_rsq(p);

    // 2*asin(side): A&S 4.4.45 deg-3, coefficients pre-doubled
    float aa = fminf(fabsf(side), 1.0f);
    float sq = mufu_sqrt(1.0f - aa);
    float poly = -0.0374586f;
    poly = fmaf(poly, aa, 0.1485220f);
    poly = fmaf(poly, aa, -0.4242288f);
    poly = fmaf(poly, aa, 3.1414576f);
    float v = fmaf(-sq, poly, 3.14159265358979f);   // 2*asin(|side|)

    meas_out = meas;
    nang_out = copysignf(v, side);
}

__global__ void __launch_bounds__(256)
wmeasure_rot_kernel(const float4* __restrict__ inp,
                    const float4* __restrict__ ang,
                    const float4* __restrict__ lres,
                    float4* __restrict__ out_meas,
                    float4* __restrict__ out_ang) {
    int t = blockIdx.x * blockDim.x + threadIdx.x;
    int s0 = 2 * t;              // two consecutive float4 slots per thread
    int s1 = 2 * t + 1;
    uint32_t base = (uint32_t)t * 8u;

    float4 x0 = inp[s0],  x1 = inp[s1];
    float4 a0 = ang[s0],  a1 = ang[s1];
    float4 l0 = lres[s0], l1 = lres[s1];

    float xs[8] = {x0.x, x0.y, x0.z, x0.w, x1.x, x1.y, x1.z, x1.w};
    float as[8] = {a0.x, a0.y, a0.z, a0.w, a1.x, a1.y, a1.z, a1.w};
    float ls[8] = {l0.x, l0.y, l0.z, l0.w, l1.x, l1.y, l1.z, l1.w};

    float ms[8], ns[8];
#pragma unroll
    for (int j = 0; j < 8; j++)
        wmeas_elem(xs[j], as[j], ls[j], base + (uint32_t)j, ms[j], ns[j]);

    out_meas[s0] = make_float4(ms[0], ms[1], ms[2], ms[3]);
    out_meas[s1] = make_float4(ms[4], ms[5], ms[6], ms[7]);
    out_ang[s0]  = make_float4(ns[0], ns[1], ns[2], ns[3]);
    out_ang[s1]  = make_float4(ns[4], ns[5], ns[6], ns[7]);
}

extern "C" void kernel_launch(void* const* d_in, const int* in_sizes, int n_in,
                              void* d_out, int out_size) {
    const float* inp  = (const float*)d_in[0];
    const float* ang  = (const float*)d_in[1];
    const float* lres = (const float*)d_in[2];
    float* out = (float*)d_out;

    int n = in_sizes[0];                 // B*N = 33554432 (divisible by 2048)
    int threads = n / 8;
    int block = 256;
    int grid = (threads + block - 1) / block;

    wmeasure_rot_kernel<<<grid, block>>>(
        (const float4*)inp, (const float4*)ang, (const float4*)lres,
        (float4*)out, (float4*)(out + n));
}

// round 9
// speedup vs baseline: 1.4850x; 1.0400x over previous
#include <cuda_runtime.h>
#include <cstdint>

// WMeasure_Rot: elementwise quantum-measurement update.
// inputs:  d_in[0]=input f32, d_in[1]=angles f32, d_in[2]=last_res f32  (each B*N)
// output:  d_out[0:B*N) = meas_res,  d_out[B*N:2*B*N) = new_angles
//
// RNG (bit-exact): JAX threefry2x32, key=(0,42), partitionable.
// R9: packed f32x2 (FFMA2) float pipeline. Calibrated model says the binder
// is ALU rt (threefry's 20 SHF + 21 LOP3, immovable) + total issue slots.
// Pairing the float math via fma/mul/add.rn.f32x2 halves its issue-slot cost
// without touching the ALU pipe. Lanes round .rn = scalar-identical, so
// rel_err must remain exactly 3.45267e-4 (1 flip).

#define DEVINL __device__ __forceinline__

DEVINL uint32_t rotl32(uint32_t x, int d) { return __funnelshift_l(x, x, d); }

DEVINL uint32_t threefry_bits(uint32_t ctr) {
    const uint32_t ks0 = 0u;
    const uint32_t ks1 = 42u;
    const uint32_t ks2 = 0x1BD11BDAu ^ 0u ^ 42u;
    uint32_t x0 = 0u + ks0;
    uint32_t x1 = ctr + ks1;
#define TF_ROUND(r) { x0 += x1; x1 = rotl32(x1, (r)); x1 ^= x0; }
    TF_ROUND(13) TF_ROUND(15) TF_ROUND(26) TF_ROUND(6)
    x0 += ks1; x1 += ks2 + 1u;
    TF_ROUND(17) TF_ROUND(29) TF_ROUND(16) TF_ROUND(24)
    x0 += ks2; x1 += ks0 + 2u;
    TF_ROUND(13) TF_ROUND(15) TF_ROUND(26) TF_ROUND(6)
    x0 += ks0; x1 += ks1 + 3u;
    TF_ROUND(17) TF_ROUND(29) TF_ROUND(16) TF_ROUND(24)
    x0 += ks1; x1 += ks2 + 4u;
    TF_ROUND(13) TF_ROUND(15) TF_ROUND(26) TF_ROUND(6)
    x0 += ks2; x1 += ks0 + 5u;
#undef TF_ROUND
    return x0 ^ x1;
}

DEVINL float mufu_ex2(float x)  { float r; asm("ex2.approx.f32 %0, %1;"  : "=f"(r) : "f"(x)); return r; }
DEVINL float mufu_rcp(float x)  { float r; asm("rcp.approx.f32 %0, %1;"  : "=f"(r) : "f"(x)); return r; }
DEVINL float mufu_rsq(float x)  { float r; asm("rsqrt.approx.f32 %0, %1;": "=f"(r) : "f"(x)); return r; }
DEVINL float mufu_sqrt(float x) { float r; asm("sqrt.approx.f32 %0, %1;" : "=f"(r) : "f"(x)); return r; }
DEVINL float mufu_sin(float x)  { float r; asm("sin.approx.f32 %0, %1;"  : "=f"(r) : "f"(x)); return r; }

// ---- packed f32x2 helpers (Blackwell FFMA2 path) ----
struct F2 { uint64_t v; };
DEVINL F2 pk2(float lo, float hi) { F2 r; asm("mov.b64 %0, {%1, %2};" : "=l"(r.v) : "f"(lo), "f"(hi)); return r; }
DEVINL void upk2(F2 p, float& lo, float& hi) { asm("mov.b64 {%0, %1}, %2;" : "=f"(lo), "=f"(hi) : "l"(p.v)); }
DEVINL F2 bc2(float c) { F2 r; asm("mov.b64 %0, {%1, %1};" : "=l"(r.v) : "f"(c)); return r; }
DEVINL F2 fma2(F2 a, F2 b, F2 c) { F2 d; asm("fma.rn.f32x2 %0, %1, %2, %3;" : "=l"(d.v) : "l"(a.v), "l"(b.v), "l"(c.v)); return d; }
DEVINL F2 mul2(F2 a, F2 b) { F2 d; asm("mul.rn.f32x2 %0, %1, %2;" : "=l"(d.v) : "l"(a.v), "l"(b.v)); return d; }
DEVINL F2 add2(F2 a, F2 b) { F2 d; asm("add.rn.f32x2 %0, %1, %2;" : "=l"(d.v) : "l"(a.v), "l"(b.v)); return d; }

struct Cns {
    F2 pi4, mpi4, half, pi2, msing, hsing, c15, mkhdf, kmid;
    F2 nc3, nc2, nc1, nc0, pi;
};

DEVINL void wmeas_pair(float x_a, float x_b, F2 a2, F2 l2, uint32_t idx,
                       const Cns& C,
                       float& m_a, float& m_b, float& n_a, float& n_b) {
    const float FOURLOG2E = 5.770780163555852f;   // 4/ln(2)

    // scalar: RNG + tanh front (feeds MUFU)
    uint32_t ba = threefry_bits(idx);
    uint32_t bb = threefry_bits(idx + 1u);
    float fa = __uint_as_float((ba >> 9) | 0x3f800000u);   // in [1,2)
    float fb = __uint_as_float((bb >> 9) | 0x3f800000u);

    float ea = mufu_ex2(x_a * FOURLOG2E);
    float eb = mufu_ex2(x_b * FOURLOG2E);
    float ra = mufu_rcp(ea + 1.0f);
    float rb = mufu_rcp(eb + 1.0f);

    // packed: ht = 0.5*a + fma(pi/4, lr, -pi/4) + (pi/2)*r
    F2 r2  = pk2(ra, rb);
    F2 bk2 = fma2(C.pi4, l2, C.mpi4);       // exact for lr in {+1,-1}
    F2 b22 = fma2(C.half, a2, bk2);
    F2 ht2 = fma2(C.pi2, r2, b22);

    float hta, htb; upk2(ht2, hta, htb);
    float sa = mufu_sin(hta);
    float sb = mufu_sin(htb);

    F2 s2   = pk2(sa, sb);
    F2 gs2  = mul2(C.msing, s2);            // -SIN_G * s
    F2 hez2 = fma2(gs2, s2, C.hsing);       // (sin g * cos t)/2
    F2 thr2 = add2(hez2, C.c15);            // 1.5 + hez

    float ta, tb; upk2(thr2, ta, tb);
    float mea = (fa < ta) ? 1.0f : -1.0f;
    float meb = (fb < tb) ? 1.0f : -1.0f;

    F2 ms2 = pk2(mea, meb);
    F2 p2  = fma2(ms2, hez2, C.half);       // (1+meas*ez)/2 in [0.146,0.854]
    F2 K2  = fma2(ms2, C.mkhdf, C.kmid);

    float pa, pb; upk2(p2, pa, pb);
    float qa = mufu_rsq(pa);
    float qb = mufu_rsq(pb);

    F2 q2  = pk2(qa, qb);
    F2 sk2 = mul2(s2, K2);
    F2 sd2 = mul2(sk2, q2);                 // side

    float sda, sdb; upk2(sd2, sda, sdb);
    float aaa = fminf(fabsf(sda), 1.0f);
    float aab = fminf(fabsf(sdb), 1.0f);
    float sqa = mufu_sqrt(1.0f - aaa);
    float sqb = mufu_sqrt(1.0f - aab);

    // packed asin tail: negated-coefficient Horner absorbs the -sq
    // v = pi + sq * negHorner(aa), negHorner = -(doubled A&S 4.4.45 poly)
    F2 aa2 = pk2(aaa, aab);
    F2 sq2 = pk2(sqa, sqb);
    F2 po  = fma2(C.nc3, aa2, C.nc2);
    po     = fma2(po,    aa2, C.nc1);
    po     = fma2(po,    aa2, C.nc0);
    F2 v2  = fma2(sq2, po, C.pi);

    float va, vb; upk2(v2, va, vb);
    m_a = mea;
    m_b = meb;
    n_a = copysignf(va, sda);
    n_b = copysignf(vb, sdb);
}

__global__ void __launch_bounds__(256)
wmeasure_rot_kernel(const float4* __restrict__ inp,
                    const float4* __restrict__ ang,
                    const float4* __restrict__ lres,
                    float4* __restrict__ out_meas,
                    float4* __restrict__ out_ang) {
    Cns C;
    C.pi4   = bc2( 0.7853981633974483f);
    C.mpi4  = bc2(-0.7853981633974483f);
    C.half  = bc2( 0.5f);
    C.pi2   = bc2( 1.5707963267948966f);
    C.msing = bc2(-0.70710678f);
    C.hsing = bc2( 0.35355339f);
    C.c15   = bc2( 1.5f);
    C.mkhdf = bc2(-0.2705980500730985f);
    C.kmid  = bc2( 0.6532814824381883f);
    C.nc3   = bc2( 0.0374586f);             // negated doubled coefficients
    C.nc2   = bc2(-0.1485220f);
    C.nc1   = bc2( 0.4242288f);
    C.nc0   = bc2(-3.1414576f);
    C.pi    = bc2( 3.14159265358979f);

    int t = blockIdx.x * blockDim.x + threadIdx.x;
    int s0 = 2 * t;
    int s1 = 2 * t + 1;
    uint32_t base = (uint32_t)t * 8u;

    float4 x0 = inp[s0],  x1 = inp[s1];
    float4 a0 = ang[s0],  a1 = ang[s1];
    float4 l0 = lres[s0], l1 = lres[s1];

    float m[8], n[8];
    // pairs aligned to float4 halves: (a2,l2) packs are adjacent-register, free
    wmeas_pair(x0.x, x0.y, pk2(a0.x, a0.y), pk2(l0.x, l0.y), base + 0u, C, m[0], m[1], n[0], n[1]);
    wmeas_pair(x0.z, x0.w, pk2(a0.z, a0.w), pk2(l0.z, l0.w), base + 2u, C, m[2], m[3], n[2], n[3]);
    wmeas_pair(x1.x, x1.y, pk2(a1.x, a1.y), pk2(l1.x, l1.y), base + 4u, C, m[4], m[5], n[4], n[5]);
    wmeas_pair(x1.z, x1.w, pk2(a1.z, a1.w), pk2(l1.z, l1.w), base + 6u, C, m[6], m[7], n[6], n[7]);

    out_meas[s0] = make_float4(m[0], m[1], m[2], m[3]);
    out_meas[s1] = make_float4(m[4], m[5], m[6], m[7]);
    out_ang[s0]  = make_float4(n[0], n[1], n[2], n[3]);
    out_ang[s1]  = make_float4(n[4], n[5], n[6], n[7]);
}

extern "C" void kernel_launch(void* const* d_in, const int* in_sizes, int n_in,
                              void* d_out, int out_size) {
    const float* inp  = (const float*)d_in[0];
    const float* ang  = (const float*)d_in[1];
    const float* lres = (const float*)d_in[2];
    float* out = (float*)d_out;

    int n = in_sizes[0];                 // B*N = 33554432 (divisible by 2048)
    int threads = n / 8;
    int block = 256;
    int grid = (threads + block - 1) / block;

    wmeasure_rot_kernel<<<grid, block>>>(
        (const float4*)inp, (const float4*)ang, (const float4*)lres,
        (float4*)out, (float4*)(out + n));
}

// round 10
// speedup vs baseline: 1.5089x; 1.0162x over previous
#include <cuda_runtime.h>
#include <cstdint>

// WMeasure_Rot: elementwise quantum-measurement update.
// inputs:  d_in[0]=input f32, d_in[1]=angles f32, d_in[2]=last_res f32  (each B*N)
// output:  d_out[0:B*N) = meas_res,  d_out[B*N:2*B*N) = new_angles
//
// RNG (bit-exact): JAX threefry2x32, key=(0,42), partitionable.
// R10 = R9 (packed f32x2 float pipeline) + ALU-pipe trims:
//  * integer-domain Bernoulli test: f and thr both in [1,2) so
//    f < thr  <=>  bits < (float_bits(thr) << 9)   (exponent shifts out exactly)
//    kills the |0x3f800000 LOP3 per element. Exactly equivalent boundary.
//  * ex2 feed packed: one mul2 per pair instead of two scalar muls.
//  * threefry round 1 folded (x0 starts at 0 -> x0 = x1 rename).

#define DEVINL __device__ __forceinline__

DEVINL uint32_t rotl32(uint32_t x, int d) { return __funnelshift_l(x, x, d); }

DEVINL uint32_t threefry_bits(uint32_t ctr) {
    const uint32_t ks1 = 42u;
    const uint32_t ks2 = 0x1BD11BDAu ^ 42u;
    // x0 = 0 + ks0 = 0; round 1: x0 += x1 -> x0 = x1 (pure rename)
    uint32_t x1 = ctr + ks1;
    uint32_t x0 = x1;
    x1 = rotl32(x1, 13) ^ x0;
#define TF_ROUND(r) { x0 += x1; x1 = rotl32(x1, (r)); x1 ^= x0; }
    TF_ROUND(15) TF_ROUND(26) TF_ROUND(6)
    x0 += ks1; x1 += ks2 + 1u;
    TF_ROUND(17) TF_ROUND(29) TF_ROUND(16) TF_ROUND(24)
    x0 += ks2; x1 += 0u + 2u;
    TF_ROUND(13) TF_ROUND(15) TF_ROUND(26) TF_ROUND(6)
    x0 += 0u; x1 += ks1 + 3u;
    TF_ROUND(17) TF_ROUND(29) TF_ROUND(16) TF_ROUND(24)
    x0 += ks1; x1 += ks2 + 4u;
    TF_ROUND(13) TF_ROUND(15) TF_ROUND(26) TF_ROUND(6)
    x0 += ks2; x1 += 0u + 5u;
#undef TF_ROUND
    return x0 ^ x1;
}

DEVINL float mufu_ex2(float x)  { float r; asm("ex2.approx.f32 %0, %1;"  : "=f"(r) : "f"(x)); return r; }
DEVINL float mufu_rcp(float x)  { float r; asm("rcp.approx.f32 %0, %1;"  : "=f"(r) : "f"(x)); return r; }
DEVINL float mufu_rsq(float x)  { float r; asm("rsqrt.approx.f32 %0, %1;": "=f"(r) : "f"(x)); return r; }
DEVINL float mufu_sqrt(float x) { float r; asm("sqrt.approx.f32 %0, %1;" : "=f"(r) : "f"(x)); return r; }
DEVINL float mufu_sin(float x)  { float r; asm("sin.approx.f32 %0, %1;"  : "=f"(r) : "f"(x)); return r; }

// ---- packed f32x2 helpers (Blackwell FFMA2 path) ----
struct F2 { uint64_t v; };
DEVINL F2 pk2(float lo, float hi) { F2 r; asm("mov.b64 %0, {%1, %2};" : "=l"(r.v) : "f"(lo), "f"(hi)); return r; }
DEVINL void upk2(F2 p, float& lo, float& hi) { asm("mov.b64 {%0, %1}, %2;" : "=f"(lo), "=f"(hi) : "l"(p.v)); }
DEVINL F2 bc2(float c) { F2 r; asm("mov.b64 %0, {%1, %1};" : "=l"(r.v) : "f"(c)); return r; }
DEVINL F2 fma2(F2 a, F2 b, F2 c) { F2 d; asm("fma.rn.f32x2 %0, %1, %2, %3;" : "=l"(d.v) : "l"(a.v), "l"(b.v), "l"(c.v)); return d; }
DEVINL F2 mul2(F2 a, F2 b) { F2 d; asm("mul.rn.f32x2 %0, %1, %2;" : "=l"(d.v) : "l"(a.v), "l"(b.v)); return d; }
DEVINL F2 add2(F2 a, F2 b) { F2 d; asm("add.rn.f32x2 %0, %1, %2;" : "=l"(d.v) : "l"(a.v), "l"(b.v)); return d; }

struct Cns {
    F2 pi4, mpi4, half, pi2, msing, hsing, c15, mkhdf, kmid;
    F2 nc3, nc2, nc1, nc0, pi, flog;
};

DEVINL void wmeas_pair(F2 x2, F2 a2, F2 l2, uint32_t idx,
                       const Cns& C,
                       float& m_a, float& m_b, float& n_a, float& n_b) {
    // scalar: RNG (feeds integer compare only)
    uint32_t ba = threefry_bits(idx);
    uint32_t bb = threefry_bits(idx + 1u);

    // packed ex2 feed: x * 4/ln2
    F2 xe2 = mul2(x2, C.flog);
    float xea, xeb; upk2(xe2, xea, xeb);
    float ea = mufu_ex2(xea);
    float eb = mufu_ex2(xeb);
    float ra = mufu_rcp(ea + 1.0f);
    float rb = mufu_rcp(eb + 1.0f);

    // packed: ht = 0.5*a + fma(pi/4, lr, -pi/4) + (pi/2)*r
    F2 r2  = pk2(ra, rb);
    F2 bk2 = fma2(C.pi4, l2, C.mpi4);       // exact for lr in {+1,-1}
    F2 b22 = fma2(C.half, a2, bk2);
    F2 ht2 = fma2(C.pi2, r2, b22);

    float hta, htb; upk2(ht2, hta, htb);
    float sa = mufu_sin(hta);
    float sb = mufu_sin(htb);

    F2 s2   = pk2(sa, sb);
    F2 gs2  = mul2(C.msing, s2);            // -SIN_G * s
    F2 hez2 = fma2(gs2, s2, C.hsing);       // (sin g * cos t)/2
    F2 thr2 = add2(hez2, C.c15);            // thr = 1.5 + hez, in [1.146,1.854]

    // integer-domain Bernoulli: f < thr  <=>  bits < (thr_bits << 9)
    float ta, tb; upk2(thr2, ta, tb);
    float mea = (ba < (__float_as_uint(ta) << 9)) ? 1.0f : -1.0f;
    float meb = (bb < (__float_as_uint(tb) << 9)) ? 1.0f : -1.0f;

    F2 ms2 = pk2(mea, meb);
    F2 p2  = fma2(ms2, hez2, C.half);       // (1+meas*ez)/2 in [0.146,0.854]
    F2 K2  = fma2(ms2, C.mkhdf, C.kmid);

    float pa, pb; upk2(p2, pa, pb);
    float qa = mufu_rsq(pa);
    float qb = mufu_rsq(pb);

    F2 q2  = pk2(qa, qb);
    F2 sk2 = mul2(s2, K2);
    F2 sd2 = mul2(sk2, q2);                 // side

    float sda, sdb; upk2(sd2, sda, sdb);
    float aaa = fminf(fabsf(sda), 1.0f);
    float aab = fminf(fabsf(sdb), 1.0f);
    float sqa = mufu_sqrt(1.0f - aaa);
    float sqb = mufu_sqrt(1.0f - aab);

    // packed asin tail: negated-coefficient Horner absorbs the -sq
    F2 aa2 = pk2(aaa, aab);
    F2 sq2 = pk2(sqa, sqb);
    F2 po  = fma2(C.nc3, aa2, C.nc2);
    po     = fma2(po,    aa2, C.nc1);
    po     = fma2(po,    aa2, C.nc0);
    F2 v2  = fma2(sq2, po, C.pi);

    float va, vb; upk2(v2, va, vb);
    m_a = mea;
    m_b = meb;
    n_a = copysignf(va, sda);
    n_b = copysignf(vb, sdb);
}

__global__ void __launch_bounds__(256)
wmeasure_rot_kernel(const float4* __restrict__ inp,
                    const float4* __restrict__ ang,
                    const float4* __restrict__ lres,
                    float4* __restrict__ out_meas,
                    float4* __restrict__ out_ang) {
    Cns C;
    C.pi4   = bc2( 0.7853981633974483f);
    C.mpi4  = bc2(-0.7853981633974483f);
    C.half  = bc2( 0.5f);
    C.pi2   = bc2( 1.5707963267948966f);
    C.msing = bc2(-0.70710678f);
    C.hsing = bc2( 0.35355339f);
    C.c15   = bc2( 1.5f);
    C.mkhdf = bc2(-0.2705980500730985f);
    C.kmid  = bc2( 0.6532814824381883f);
    C.nc3   = bc2( 0.0374586f);             // negated doubled coefficients
    C.nc2   = bc2(-0.1485220f);
    C.nc1   = bc2( 0.4242288f);
    C.nc0   = bc2(-3.1414576f);
    C.pi    = bc2( 3.14159265358979f);
    C.flog  = bc2( 5.770780163555852f);     // 4/ln(2)

    int t = blockIdx.x * blockDim.x + threadIdx.x;
    int s0 = 2 * t;
    int s1 = 2 * t + 1;
    uint32_t base = (uint32_t)t * 8u;

    float4 x0 = inp[s0],  x1 = inp[s1];
    float4 a0 = ang[s0],  a1 = ang[s1];
    float4 l0 = lres[s0], l1 = lres[s1];

    float m[8], n[8];
    wmeas_pair(pk2(x0.x, x0.y), pk2(a0.x, a0.y), pk2(l0.x, l0.y), base + 0u, C, m[0], m[1], n[0], n[1]);
    wmeas_pair(pk2(x0.z, x0.w), pk2(a0.z, a0.w), pk2(l0.z, l0.w), base + 2u, C, m[2], m[3], n[2], n[3]);
    wmeas_pair(pk2(x1.x, x1.y), pk2(a1.x, a1.y), pk2(l1.x, l1.y), base + 4u, C, m[4], m[5], n[4], n[5]);
    wmeas_pair(pk2(x1.z, x1.w), pk2(a1.z, a1.w), pk2(l1.z, l1.w), base + 6u, C, m[6], m[7], n[6], n[7]);

    out_meas[s0] = make_float4(m[0], m[1], m[2], m[3]);
    out_meas[s1] = make_float4(m[4], m[5], m[6], m[7]);
    out_ang[s0]  = make_float4(n[0], n[1], n[2], n[3]);
    out_ang[s1]  = make_float4(n[4], n[5], n[6], n[7]);
}

extern "C" void kernel_launch(void* const* d_in, const int* in_sizes, int n_in,
                              void* d_out, int out_size) {
    const float* inp  = (const float*)d_in[0];
    const float* ang  = (const float*)d_in[1];
    const float* lres = (const float*)d_in[2];
    float* out = (float*)d_out;

    int n = in_sizes[0];                 // B*N = 33554432 (divisible by 2048)
    int threads = n / 8;
    int block = 256;
    int grid = (threads + block - 1) / block;

    wmeasure_rot_kernel<<<grid, block>>>(
        (const float4*)inp, (const float4*)ang, (const float4*)lres,
        (float4*)out, (float4*)(out + n));
}

// round 11
// speedup vs baseline: 1.5098x; 1.0006x over previous
#include <cuda_runtime.h>
#include <cstdint>

// WMeasure_Rot: elementwise quantum-measurement update.
// inputs:  d_in[0]=input f32, d_in[1]=angles f32, d_in[2]=last_res f32  (each B*N)
// output:  d_out[0:B*N) = meas_res,  d_out[B*N:2*B*N) = new_angles
//
// RNG (bit-exact): JAX threefry2x32, key=(0,42), partitionable.
// R10 = R9 (packed f32x2 float pipeline) + ALU-pipe trims:
//  * integer-domain Bernoulli test: f and thr both in [1,2) so
//    f < thr  <=>  bits < (float_bits(thr) << 9)   (exponent shifts out exactly)
//    kills the |0x3f800000 LOP3 per element. Exactly equivalent boundary.
//  * ex2 feed packed: one mul2 per pair instead of two scalar muls.
//  * threefry round 1 folded (x0 starts at 0 -> x0 = x1 rename).

#define DEVINL __device__ __forceinline__

DEVINL uint32_t rotl32(uint32_t x, int d) { return __funnelshift_l(x, x, d); }

DEVINL uint32_t threefry_bits(uint32_t ctr) {
    const uint32_t ks1 = 42u;
    const uint32_t ks2 = 0x1BD11BDAu ^ 42u;
    // x0 = 0 + ks0 = 0; round 1: x0 += x1 -> x0 = x1 (pure rename)
    uint32_t x1 = ctr + ks1;
    uint32_t x0 = x1;
    x1 = rotl32(x1, 13) ^ x0;
#define TF_ROUND(r) { x0 += x1; x1 = rotl32(x1, (r)); x1 ^= x0; }
    TF_ROUND(15) TF_ROUND(26) TF_ROUND(6)
    x0 += ks1; x1 += ks2 + 1u;
    TF_ROUND(17) TF_ROUND(29) TF_ROUND(16) TF_ROUND(24)
    x0 += ks2; x1 += 0u + 2u;
    TF_ROUND(13) TF_ROUND(15) TF_ROUND(26) TF_ROUND(6)
    x0 += 0u; x1 += ks1 + 3u;
    TF_ROUND(17) TF_ROUND(29) TF_ROUND(16) TF_ROUND(24)
    x0 += ks1; x1 += ks2 + 4u;
    TF_ROUND(13) TF_ROUND(15) TF_ROUND(26) TF_ROUND(6)
    x0 += ks2; x1 += 0u + 5u;
#undef TF_ROUND
    return x0 ^ x1;
}

DEVINL float mufu_ex2(float x)  { float r; asm("ex2.approx.f32 %0, %1;"  : "=f"(r) : "f"(x)); return r; }
DEVINL float mufu_rcp(float x)  { float r; asm("rcp.approx.f32 %0, %1;"  : "=f"(r) : "f"(x)); return r; }
DEVINL float mufu_rsq(float x)  { float r; asm("rsqrt.approx.f32 %0, %1;": "=f"(r) : "f"(x)); return r; }
DEVINL float mufu_sqrt(float x) { float r; asm("sqrt.approx.f32 %0, %1;" : "=f"(r) : "f"(x)); return r; }
DEVINL float mufu_sin(float x)  { float r; asm("sin.approx.f32 %0, %1;"  : "=f"(r) : "f"(x)); return r; }

// ---- packed f32x2 helpers (Blackwell FFMA2 path) ----
struct F2 { uint64_t v; };
DEVINL F2 pk2(float lo, float hi) { F2 r; asm("mov.b64 %0, {%1, %2};" : "=l"(r.v) : "f"(lo), "f"(hi)); return r; }
DEVINL void upk2(F2 p, float& lo, float& hi) { asm("mov.b64 {%0, %1}, %2;" : "=f"(lo), "=f"(hi) : "l"(p.v)); }
DEVINL F2 bc2(float c) { F2 r; asm("mov.b64 %0, {%1, %1};" : "=l"(r.v) : "f"(c)); return r; }
DEVINL F2 fma2(F2 a, F2 b, F2 c) { F2 d; asm("fma.rn.f32x2 %0, %1, %2, %3;" : "=l"(d.v) : "l"(a.v), "l"(b.v), "l"(c.v)); return d; }
DEVINL F2 mul2(F2 a, F2 b) { F2 d; asm("mul.rn.f32x2 %0, %1, %2;" : "=l"(d.v) : "l"(a.v), "l"(b.v)); return d; }
DEVINL F2 add2(F2 a, F2 b) { F2 d; asm("add.rn.f32x2 %0, %1, %2;" : "=l"(d.v) : "l"(a.v), "l"(b.v)); return d; }

struct Cns {
    F2 pi4, mpi4, half, pi2, msing, hsing, c15, mkhdf, kmid;
    F2 nc3, nc2, nc1, nc0, pi, flog;
};

DEVINL void wmeas_pair(F2 x2, F2 a2, F2 l2, uint32_t idx,
                       const Cns& C,
                       float& m_a, float& m_b, float& n_a, float& n_b) {
    // scalar: RNG (feeds integer compare only)
    uint32_t ba = threefry_bits(idx);
    uint32_t bb = threefry_bits(idx + 1u);

    // packed ex2 feed: x * 4/ln2
    F2 xe2 = mul2(x2, C.flog);
    float xea, xeb; upk2(xe2, xea, xeb);
    float ea = mufu_ex2(xea);
    float eb = mufu_ex2(xeb);
    float ra = mufu_rcp(ea + 1.0f);
    float rb = mufu_rcp(eb + 1.0f);

    // packed: ht = 0.5*a + fma(pi/4, lr, -pi/4) + (pi/2)*r
    F2 r2  = pk2(ra, rb);
    F2 bk2 = fma2(C.pi4, l2, C.mpi4);       // exact for lr in {+1,-1}
    F2 b22 = fma2(C.half, a2, bk2);
    F2 ht2 = fma2(C.pi2, r2, b22);

    float hta, htb; upk2(ht2, hta, htb);
    float sa = mufu_sin(hta);
    float sb = mufu_sin(htb);

    F2 s2   = pk2(sa, sb);
    F2 gs2  = mul2(C.msing, s2);            // -SIN_G * s
    F2 hez2 = fma2(gs2, s2, C.hsing);       // (sin g * cos t)/2
    F2 thr2 = add2(hez2, C.c15);            // thr = 1.5 + hez, in [1.146,1.854]

    // integer-domain Bernoulli: f < thr  <=>  bits < (thr_bits << 9)
    float ta, tb; upk2(thr2, ta, tb);
    float mea = (ba < (__float_as_uint(ta) << 9)) ? 1.0f : -1.0f;
    float meb = (bb < (__float_as_uint(tb) << 9)) ? 1.0f : -1.0f;

    F2 ms2 = pk2(mea, meb);
    F2 p2  = fma2(ms2, hez2, C.half);       // (1+meas*ez)/2 in [0.146,0.854]
    F2 K2  = fma2(ms2, C.mkhdf, C.kmid);

    float pa, pb; upk2(p2, pa, pb);
    float qa = mufu_rsq(pa);
    float qb = mufu_rsq(pb);

    F2 q2  = pk2(qa, qb);
    F2 sk2 = mul2(s2, K2);
    F2 sd2 = mul2(sk2, q2);                 // side

    float sda, sdb; upk2(sd2, sda, sdb);
    float aaa = fminf(fabsf(sda), 1.0f);
    float aab = fminf(fabsf(sdb), 1.0f);
    float sqa = mufu_sqrt(1.0f - aaa);
    float sqb = mufu_sqrt(1.0f - aab);

    // packed asin tail: negated-coefficient Horner absorbs the -sq
    F2 aa2 = pk2(aaa, aab);
    F2 sq2 = pk2(sqa, sqb);
    F2 po  = fma2(C.nc3, aa2, C.nc2);
    po     = fma2(po,    aa2, C.nc1);
    po     = fma2(po,    aa2, C.nc0);
    F2 v2  = fma2(sq2, po, C.pi);

    float va, vb; upk2(v2, va, vb);
    m_a = mea;
    m_b = meb;
    n_a = copysignf(va, sda);
    n_b = copysignf(vb, sdb);
}

__global__ void __launch_bounds__(256)
wmeasure_rot_kernel(const float4* __restrict__ inp,
                    const float4* __restrict__ ang,
                    const float4* __restrict__ lres,
                    float4* __restrict__ out_meas,
                    float4* __restrict__ out_ang) {
    Cns C;
    C.pi4   = bc2( 0.7853981633974483f);
    C.mpi4  = bc2(-0.7853981633974483f);
    C.half  = bc2( 0.5f);
    C.pi2   = bc2( 1.5707963267948966f);
    C.msing = bc2(-0.70710678f);
    C.hsing = bc2( 0.35355339f);
    C.c15   = bc2( 1.5f);
    C.mkhdf = bc2(-0.2705980500730985f);
    C.kmid  = bc2( 0.6532814824381883f);
    C.nc3   = bc2( 0.0374586f);             // negated doubled coefficients
    C.nc2   = bc2(-0.1485220f);
    C.nc1   = bc2( 0.4242288f);
    C.nc0   = bc2(-3.1414576f);
    C.pi    = bc2( 3.14159265358979f);
    C.flog  = bc2( 5.770780163555852f);     // 4/ln(2)

    int t = blockIdx.x * blockDim.x + threadIdx.x;
    int s0 = 2 * t;
    int s1 = 2 * t + 1;
    uint32_t base = (uint32_t)t * 8u;

    float4 x0 = inp[s0],  x1 = inp[s1];
    float4 a0 = ang[s0],  a1 = ang[s1];
    float4 l0 = lres[s0], l1 = lres[s1];

    float m[8], n[8];
    wmeas_pair(pk2(x0.x, x0.y), pk2(a0.x, a0.y), pk2(l0.x, l0.y), base + 0u, C, m[0], m[1], n[0], n[1]);
    wmeas_pair(pk2(x0.z, x0.w), pk2(a0.z, a0.w), pk2(l0.z, l0.w), base + 2u, C, m[2], m[3], n[2], n[3]);
    wmeas_pair(pk2(x1.x, x1.y), pk2(a1.x, a1.y), pk2(l1.x, l1.y), base + 4u, C, m[4], m[5], n[4], n[5]);
    wmeas_pair(pk2(x1.z, x1.w), pk2(a1.z, a1.w), pk2(l1.z, l1.w), base + 6u, C, m[6], m[7], n[6], n[7]);

    out_meas[s0] = make_float4(m[0], m[1], m[2], m[3]);
    out_meas[s1] = make_float4(m[4], m[5], m[6], m[7]);
    out_ang[s0]  = make_float4(n[0], n[1], n[2], n[3]);
    out_ang[s1]  = make_float4(n[4], n[5], n[6], n[7]);
}

extern "C" void kernel_launch(void* const* d_in, const int* in_sizes, int n_in,
                              void* d_out, int out_size) {
    const float* inp  = (const float*)d_in[0];
    const float* ang  = (const float*)d_in[1];
    const float* lres = (const float*)d_in[2];
    float* out = (float*)d_out;

    int n = in_sizes[0];                 // B*N = 33554432 (divisible by 2048)
    int threads = n / 8;
    int block = 256;
    int grid = (threads + block - 1) / block;

    wmeasure_rot_kernel<<<grid, block>>>(
        (const float4*)inp, (const float4*)ang, (const float4*)lres,
        (float4*)out, (float4*)(out + n));
}